// round 7
// baseline (speedup 1.0000x reference)
#include <cuda_runtime.h>
#include <cstdint>

#define DEV static __device__ __forceinline__
typedef unsigned __int128 u128;

__device__ float g_s[256 * 4096];
__device__ float g_m[256 * 12];
__device__ float g_t[256 * 12];
__device__ unsigned char g_is9[10000];
__device__ unsigned char g_group[10000];
__device__ float g_bias[10000];
__device__ unsigned int g_cand[10048];
__device__ unsigned char g_accept[10048];
__device__ unsigned long long g_D[1];

// ---------------- PCG64 (numpy default_rng) ----------------
DEV u128 PCG_MULT() {
  return (((u128)0x2360ED051FC65DA4ULL) << 64) | 0x4385DF649FCCF645ULL;
}
DEV uint32_t hashmix(uint32_t v, uint32_t& hc) {
  v ^= hc; hc *= 0x931e8875u; v *= hc; v ^= v >> 16; return v;
}
DEV uint32_t mix32(uint32_t x, uint32_t y) {
  uint32_t r = 0xca01f9ddu * x - 0x4973f715u * y; r ^= r >> 16; return r;
}
DEV void pcg_seed(u128& state, u128& inc) {
  uint32_t pool[4]; uint32_t hc = 0x43b0d7e5u;
  for (int i = 0; i < 4; ++i) pool[i] = hashmix(0u, hc);
  for (int s = 0; s < 4; ++s)
    for (int d2 = 0; d2 < 4; ++d2)
      if (s != d2) pool[d2] = mix32(pool[d2], hashmix(pool[s], hc));
  uint32_t hc2 = 0x8b51f9ddu; uint32_t w[8];
  for (int i = 0; i < 8; ++i) {
    uint32_t dv = pool[i & 3];
    dv ^= hc2; hc2 *= 0x58f38dedu; dv *= hc2; dv ^= dv >> 16; w[i] = dv;
  }
  u128 initstate = (((u128)((uint64_t)w[0] | ((uint64_t)w[1] << 32))) << 64) |
                   ((uint64_t)w[2] | ((uint64_t)w[3] << 32));
  u128 initseq   = (((u128)((uint64_t)w[4] | ((uint64_t)w[5] << 32))) << 64) |
                   ((uint64_t)w[6] | ((uint64_t)w[7] << 32));
  inc = (initseq << 1) | (u128)1;
  state = inc; state += initstate;
  state = state * PCG_MULT() + inc;
}
DEV u128 pcg_advance(u128 state, u128 inc, uint64_t delta) {
  u128 cm = PCG_MULT(), cp = inc, am = (u128)1, ap = (u128)0;
  while (delta) {
    if (delta & 1) { am = am * cm; ap = ap * cm + cp; }
    cp = (cm + (u128)1) * cp; cm = cm * cm; delta >>= 1;
  }
  return am * state + ap;
}
DEV uint64_t pcg_out(u128 st) {
  unsigned rot = (unsigned)(st >> 122);
  uint64_t x = (uint64_t)(st >> 64) ^ (uint64_t)st;
  return (x >> rot) | (x << ((64 - rot) & 63));
}
DEV uint64_t draw64(u128 s0, u128 inc, uint64_t k) {
  return pcg_out(pcg_advance(s0, inc, k + 1));
}
DEV uint32_t draw32(u128 s0, u128 inc, uint64_t j) {
  uint64_t v = draw64(s0, inc, j >> 1);
  return (j & 1) ? (uint32_t)(v >> 32) : (uint32_t)v;
}

// ---------------- config kernels ----------------
__global__ void cfg1_kernel() {
  int j = blockIdx.x * blockDim.x + threadIdx.x;
  if (j >= 20048) return;
  u128 s0, inc; pcg_seed(s0, inc);
  unsigned int u = draw32(s0, inc, (uint64_t)j);
  if (j < 10000) {
    g_is9[j] = (unsigned char)(u >> 31);           // Lemire rng_excl=2
  } else {
    int c = j - 10000;                             // Lemire rng_excl=6
    unsigned long long m = (unsigned long long)u * 6ull;
    g_cand[c] = (unsigned int)(m >> 32);
    g_accept[c] = ((unsigned int)m >= 4u) ? 1 : 0;
  }
}
__global__ void cfg2_kernel() {
  __shared__ int wsum[32];
  int t = threadIdx.x;                // 1024 threads, 1 block
  const int PER = 10;
  int base = t * PER;
  unsigned char acc[PER]; int cnt = 0;
  for (int k = 0; k < PER; ++k) {
    int idx = base + k;
    unsigned char a = (idx < 10048) ? g_accept[idx] : (unsigned char)0;
    acc[k] = a; cnt += a;
  }
  int lane = t & 31, wid = t >> 5;
  int inc = cnt;
  for (int o = 1; o < 32; o <<= 1) {
    int n = __shfl_up_sync(0xffffffffu, inc, o);
    if (lane >= o) inc += n;
  }
  if (lane == 31) wsum[wid] = inc;
  __syncthreads();
  if (wid == 0) {
    int v = wsum[lane];
    for (int o = 1; o < 32; o <<= 1) {
      int n = __shfl_up_sync(0xffffffffu, v, o);
      if (lane >= o) v += n;
    }
    wsum[lane] = v;
  }
  __syncthreads();
  int excl = inc - cnt + (wid ? wsum[wid - 1] : 0);
  for (int k = 0; k < PER; ++k) {
    int idx = base + k;
    if (idx < 10048 && acc[k]) {
      if (excl < 10000) {
        g_group[excl] = (unsigned char)(g_is9[excl] * 6 + g_cand[idx]);
        if (excl == 9999) {
          unsigned long long total32 = 10000ull + (unsigned long long)(idx + 1);
          g_D[0] = (total32 + 1ull) >> 1;
        }
      }
      ++excl;
    }
  }
}
__global__ void cfg3_kernel() {
  int i = blockIdx.x * blockDim.x + threadIdx.x;
  if (i >= 10000) return;
  u128 s0, inc; pcg_seed(s0, inc);
  unsigned long long u = draw64(s0, inc, g_D[0] + (unsigned long long)i);
  double dv = (double)(u >> 11) * (1.0 / 9007199254740992.0);
  g_bias[i] = (float)(-1.0 + 2.0 * dv);
}

// ---------------- channel sum ----------------
__global__ void sum_kernel(const float* __restrict__ x) {
  int idx = blockIdx.x * blockDim.x + threadIdx.x;
  if (idx >= 256 * 1024) return;
  int b = idx >> 10, l4 = idx & 1023;
  const float4* xb = (const float4*)(x + (size_t)b * 23 * 4096) + l4;
  float4 a = __ldcs(xb);
#pragma unroll
  for (int c = 1; c < 23; ++c) {
    float4 v = __ldcs(xb + (size_t)c * 1024);
    a.x += v.x; a.y += v.y; a.z += v.z; a.w += v.w;
  }
  ((float4*)g_s)[(size_t)b * 1024 + l4] = a;
}

// ---------------- order-statistic helpers ----------------
DEV unsigned int f2ord(float f) {
  unsigned int b = __float_as_uint(f);
  return (b & 0x80000000u) ? ~b : (b | 0x80000000u);
}

// dual-K conv for one dilation: r7 = 7-tap, r9 = r7 + outer two taps
template <int D>
DEV void conv2K(const float* S, int t, float* r7, float* r9) {
#pragma unroll
  for (int i = 0; i < 16; ++i) {
    int l = t + i * 256 + 128;
    float a = S[l - 3 * D];
    a += S[l - 2 * D]; a += S[l - D]; a += S[l]; a += S[l + D];
    a += S[l + 2 * D]; a += S[l + 3 * D];
    r7[i] = a;
    r9[i] = a + S[l - 4 * D] + S[l + 4 * D];
  }
}

// cold exact path: keys in U; builds pass-0 histogram, radix-selects rank 1351,
// counts(<=key); flag = count < 2704 (i.e. v[1351] < v[2703]).
__device__ __noinline__ void fallback_select(unsigned int* U, unsigned int* hist,
                                             unsigned int* wt, int* sel, int* rci,
                                             int t, int gi) {
  int lane = t & 31, wid = t >> 5;
  hist[t] = 0;
  __syncthreads();
  for (int i = 0; i < 16; ++i)
    atomicAdd(&hist[U[t + i * 256] >> 24], 1u);
  __syncthreads();

#define SCAN_SELECT(rr)                                                        \
  {                                                                            \
    unsigned int oa = hist[t]; unsigned int a = oa;                            \
    for (int o = 1; o < 32; o <<= 1) {                                         \
      unsigned int na = __shfl_up_sync(0xffffffffu, a, o);                     \
      if (lane >= o) a += na;                                                  \
    }                                                                          \
    if (lane == 31) wt[wid] = a;                                               \
    __syncthreads();                                                           \
    if (wid == 0) {                                                            \
      unsigned int va = (lane < 8) ? wt[lane] : 0u;                            \
      for (int o = 1; o < 8; o <<= 1) {                                        \
        unsigned int na = __shfl_up_sync(0xffffffffu, va, o);                  \
        if (lane >= o) va += na;                                               \
      }                                                                        \
      if (lane < 8) wt[lane] = va;                                             \
    }                                                                          \
    __syncthreads();                                                           \
    a += wid ? wt[wid - 1] : 0u;                                               \
    unsigned int lo = a - oa;                                                  \
    if ((unsigned)(rr) >= lo && (unsigned)(rr) < a) { sel[0] = t; sel[1] = (int)lo; } \
    __syncthreads();                                                           \
  }

  int rA = 1351; unsigned int pA = 0;
  SCAN_SELECT(rA);
  pA = ((unsigned int)sel[0]) << 24; rA -= sel[1];

  for (int p = 1; p < 4; ++p) {
    int shift = 24 - 8 * p;
    unsigned int maskHi = 0xFFFFFFFFu << (32 - 8 * p);
    hist[t] = 0;
    __syncthreads();
    for (int i = 0; i < 16; ++i) {
      unsigned int key = U[t + i * 256];
      if (((key ^ pA) & maskHi) == 0)
        atomicAdd(&hist[(key >> shift) & 255u], 1u);
    }
    __syncthreads();
    SCAN_SELECT(rA);
    pA |= ((unsigned int)sel[0]) << shift; rA -= sel[1];
  }

  int cnt = 0;
  for (int i = 0; i < 16; ++i) cnt += (U[t + i * 256] <= pA) ? 1 : 0;
  for (int o = 16; o; o >>= 1) cnt += __shfl_xor_sync(0xffffffffu, cnt, o);
  if (lane == 0) rci[wid] = cnt;
  __syncthreads();
  if (t == 0) {
    int total = 0;
    for (int i = 0; i < 8; ++i) total += rci[i];
    g_t[gi] = (total < 2704) ? 1.0f : 0.0f;
  }
#undef SCAN_SELECT
}

// ---------------- main per-(batch,dilation) kernel: both K=7 and K=9 ----------------
// Hot path: conv -> {max,sum} reduce -> pivot=mean -> count(<=pivot); if count
// in [1352,2703] then v[1351] <= pivot < v[2703] => flag=1, exactly certified.
// Cold path (never taken on continuous data): full radix select.
__global__ void __launch_bounds__(256) main_kernel() {
  __shared__ __align__(16) unsigned int buf[4352];  // pad128 | data4096 | pad128
  __shared__ unsigned int hist[256];
  __shared__ unsigned int wt[8];
  __shared__ int sel[2];
  __shared__ float redA[8], redB[8], sumA[8], sumB[8];
  __shared__ float pivots[2];
  __shared__ int rci[8], rc2[8];
  __shared__ int fbMask[1];

  int b = blockIdx.x, dexp = blockIdx.y;
  int t = threadIdx.x, lane = t & 31, wid = t >> 5;

  float* S = (float*)buf;
  unsigned int* U = buf + 128;

  if (t < 128) buf[t] = 0; else buf[4096 + t] = 0;
  {
    const float4* src = (const float4*)(g_s + (size_t)b * 4096);
    float4* dstS = (float4*)(S + 128);
#pragma unroll
    for (int i = 0; i < 4; ++i) dstS[t + i * 256] = src[t + i * 256];
  }
  __syncthreads();

  float r7[16], r9[16];
  switch (dexp) {
    case 0:  conv2K<1>(S, t, r7, r9);  break;
    case 1:  conv2K<2>(S, t, r7, r9);  break;
    case 2:  conv2K<4>(S, t, r7, r9);  break;
    case 3:  conv2K<8>(S, t, r7, r9);  break;
    case 4:  conv2K<16>(S, t, r7, r9); break;
    default: conv2K<32>(S, t, r7, r9); break;
  }

  // per-thread max + sum for both groups
  float mxA = r7[0], mxB = r9[0], smA = r7[0], smB = r9[0];
#pragma unroll
  for (int i = 1; i < 16; ++i) {
    mxA = fmaxf(mxA, r7[i]); smA += r7[i];
    mxB = fmaxf(mxB, r9[i]); smB += r9[i];
  }
  for (int o = 16; o; o >>= 1) {
    mxA = fmaxf(mxA, __shfl_xor_sync(0xffffffffu, mxA, o));
    mxB = fmaxf(mxB, __shfl_xor_sync(0xffffffffu, mxB, o));
    smA += __shfl_xor_sync(0xffffffffu, smA, o);
    smB += __shfl_xor_sync(0xffffffffu, smB, o);
  }
  if (lane == 0) { redA[wid] = mxA; redB[wid] = mxB; sumA[wid] = smA; sumB[wid] = smB; }
  __syncthreads();

  int giA = b * 12 + dexp, giB = b * 12 + 6 + dexp;
  if (t == 0) {
    float bmA = redA[0], bmB = redB[0], tsA = sumA[0], tsB = sumB[0];
#pragma unroll
    for (int i = 1; i < 8; ++i) {
      bmA = fmaxf(bmA, redA[i]); bmB = fmaxf(bmB, redB[i]);
      tsA += sumA[i]; tsB += sumB[i];
    }
    g_m[giA] = bmA; g_m[giB] = bmB;
    pivots[0] = tsA * (1.0f / 4096.0f);
    pivots[1] = tsB * (1.0f / 4096.0f);
  }
  __syncthreads();

  float pA = pivots[0], pB = pivots[1];
  int cA = 0, cB = 0;
#pragma unroll
  for (int i = 0; i < 16; ++i) {
    cA += (r7[i] <= pA) ? 1 : 0;
    cB += (r9[i] <= pB) ? 1 : 0;
  }
  for (int o = 16; o; o >>= 1) {
    cA += __shfl_xor_sync(0xffffffffu, cA, o);
    cB += __shfl_xor_sync(0xffffffffu, cB, o);
  }
  if (lane == 0) { rci[wid] = cA; rc2[wid] = cB; }
  __syncthreads();

  if (t == 0) {
    int tA = 0, tB = 0;
#pragma unroll
    for (int i = 0; i < 8; ++i) { tA += rci[i]; tB += rc2[i]; }
    int mask = 0;
    if (tA >= 1352 && tA <= 2703) g_t[giA] = 1.0f; else mask |= 1;
    if (tB >= 1352 && tB <= 2703) g_t[giB] = 1.0f; else mask |= 2;
    fbMask[0] = mask;
  }
  __syncthreads();

  int mask = fbMask[0];
  if (mask == 0) return;                 // certified hot path

  if (mask & 1) {
#pragma unroll
    for (int i = 0; i < 16; ++i) U[t + i * 256] = f2ord(r7[i]);
    __syncthreads();
    fallback_select(U, hist, wt, sel, rci, t, giA);
  }
  if (mask & 2) {
    __syncthreads();
#pragma unroll
    for (int i = 0; i < 16; ++i) U[t + i * 256] = f2ord(r9[i]);
    __syncthreads();
    fallback_select(U, hist, wt, sel, rci, t, giB);
  }
}

// ---------------- output writer (float4 = 2 feature pairs) ----------------
__global__ void out_kernel(float* __restrict__ out) {
  int j = blockIdx.x * blockDim.x + threadIdx.x;   // 0..4999
  int b = blockIdx.y;
  if (j >= 5000) return;
  int i0 = 2 * j, i1 = 2 * j + 1;
  int g0 = g_group[i0], g1 = g_group[i1];
  float4 v;
  v.x = (g_m[b * 12 + g0] > g_bias[i0]) ? 1.0f : 0.0f;
  v.y = g_t[b * 12 + g0];
  v.z = (g_m[b * 12 + g1] > g_bias[i1]) ? 1.0f : 0.0f;
  v.w = g_t[b * 12 + g1];
  ((float4*)out)[(size_t)b * 5000 + j] = v;
}

extern "C" void kernel_launch(void* const* d_in, const int* in_sizes, int n_in,
                              void* d_out, int out_size) {
  const float* x = (const float*)d_in[0];
  float* out = (float*)d_out;
  cfg1_kernel<<<(20048 + 255) / 256, 256>>>();
  cfg2_kernel<<<1, 1024>>>();
  cfg3_kernel<<<(10000 + 255) / 256, 256>>>();
  sum_kernel<<<(256 * 1024 + 255) / 256, 256>>>(x);
  main_kernel<<<dim3(256, 6), 256>>>();
  out_kernel<<<dim3(20, 256), 256>>>(out);
}

// round 8
// speedup vs baseline: 1.4923x; 1.4923x over previous
#include <cuda_runtime.h>
#include <cstdint>

#define DEV static __device__ __forceinline__
typedef unsigned __int128 u128;

__device__ float g_s[256 * 4096];
__device__ float g_m[256 * 12];
__device__ float g_t[256 * 12];
__device__ unsigned char g_is9[10000];
__device__ unsigned char g_group[10000];
__device__ float g_bias[10000];
__device__ unsigned int g_cand[10048];
__device__ unsigned char g_accept[10048];
__device__ unsigned long long g_D[1];

// ---------------- PCG64 (numpy default_rng) ----------------
DEV u128 PCG_MULT() {
  return (((u128)0x2360ED051FC65DA4ULL) << 64) | 0x4385DF649FCCF645ULL;
}
DEV uint32_t hashmix(uint32_t v, uint32_t& hc) {
  v ^= hc; hc *= 0x931e8875u; v *= hc; v ^= v >> 16; return v;
}
DEV uint32_t mix32(uint32_t x, uint32_t y) {
  uint32_t r = 0xca01f9ddu * x - 0x4973f715u * y; r ^= r >> 16; return r;
}
DEV void pcg_seed(u128& state, u128& inc) {
  uint32_t pool[4]; uint32_t hc = 0x43b0d7e5u;
  for (int i = 0; i < 4; ++i) pool[i] = hashmix(0u, hc);
  for (int s = 0; s < 4; ++s)
    for (int d2 = 0; d2 < 4; ++d2)
      if (s != d2) pool[d2] = mix32(pool[d2], hashmix(pool[s], hc));
  uint32_t hc2 = 0x8b51f9ddu; uint32_t w[8];
  for (int i = 0; i < 8; ++i) {
    uint32_t dv = pool[i & 3];
    dv ^= hc2; hc2 *= 0x58f38dedu; dv *= hc2; dv ^= dv >> 16; w[i] = dv;
  }
  u128 initstate = (((u128)((uint64_t)w[0] | ((uint64_t)w[1] << 32))) << 64) |
                   ((uint64_t)w[2] | ((uint64_t)w[3] << 32));
  u128 initseq   = (((u128)((uint64_t)w[4] | ((uint64_t)w[5] << 32))) << 64) |
                   ((uint64_t)w[6] | ((uint64_t)w[7] << 32));
  inc = (initseq << 1) | (u128)1;
  state = inc; state += initstate;
  state = state * PCG_MULT() + inc;
}
DEV u128 pcg_advance(u128 state, u128 inc, uint64_t delta) {
  u128 cm = PCG_MULT(), cp = inc, am = (u128)1, ap = (u128)0;
  while (delta) {
    if (delta & 1) { am = am * cm; ap = ap * cm + cp; }
    cp = (cm + (u128)1) * cp; cm = cm * cm; delta >>= 1;
  }
  return am * state + ap;
}
DEV uint64_t pcg_out(u128 st) {
  unsigned rot = (unsigned)(st >> 122);
  uint64_t x = (uint64_t)(st >> 64) ^ (uint64_t)st;
  return (x >> rot) | (x << ((64 - rot) & 63));
}
DEV uint64_t draw64(u128 s0, u128 inc, uint64_t k) {
  return pcg_out(pcg_advance(s0, inc, k + 1));
}
DEV uint32_t draw32(u128 s0, u128 inc, uint64_t j) {
  uint64_t v = draw64(s0, inc, j >> 1);
  return (j & 1) ? (uint32_t)(v >> 32) : (uint32_t)v;
}

// ---------------- config kernels ----------------
__global__ void cfg1_kernel() {
  int j = blockIdx.x * blockDim.x + threadIdx.x;
  if (j >= 20048) return;
  u128 s0, inc; pcg_seed(s0, inc);
  unsigned int u = draw32(s0, inc, (uint64_t)j);
  if (j < 10000) {
    g_is9[j] = (unsigned char)(u >> 31);           // Lemire rng_excl=2
  } else {
    int c = j - 10000;                             // Lemire rng_excl=6
    unsigned long long m = (unsigned long long)u * 6ull;
    g_cand[c] = (unsigned int)(m >> 32);
    g_accept[c] = ((unsigned int)m >= 4u) ? 1 : 0;
  }
}
__global__ void cfg2_kernel() {
  __shared__ int wsum[32];
  int t = threadIdx.x;                // 1024 threads, 1 block
  const int PER = 10;
  int base = t * PER;
  unsigned char acc[PER]; int cnt = 0;
  for (int k = 0; k < PER; ++k) {
    int idx = base + k;
    unsigned char a = (idx < 10048) ? g_accept[idx] : (unsigned char)0;
    acc[k] = a; cnt += a;
  }
  int lane = t & 31, wid = t >> 5;
  int inc = cnt;
  for (int o = 1; o < 32; o <<= 1) {
    int n = __shfl_up_sync(0xffffffffu, inc, o);
    if (lane >= o) inc += n;
  }
  if (lane == 31) wsum[wid] = inc;
  __syncthreads();
  if (wid == 0) {
    int v = wsum[lane];
    for (int o = 1; o < 32; o <<= 1) {
      int n = __shfl_up_sync(0xffffffffu, v, o);
      if (lane >= o) v += n;
    }
    wsum[lane] = v;
  }
  __syncthreads();
  int excl = inc - cnt + (wid ? wsum[wid - 1] : 0);
  for (int k = 0; k < PER; ++k) {
    int idx = base + k;
    if (idx < 10048 && acc[k]) {
      if (excl < 10000) {
        g_group[excl] = (unsigned char)(g_is9[excl] * 6 + g_cand[idx]);
        if (excl == 9999) {
          unsigned long long total32 = 10000ull + (unsigned long long)(idx + 1);
          g_D[0] = (total32 + 1ull) >> 1;
        }
      }
      ++excl;
    }
  }
}
__global__ void cfg3_kernel() {
  int i = blockIdx.x * blockDim.x + threadIdx.x;
  if (i >= 10000) return;
  u128 s0, inc; pcg_seed(s0, inc);
  unsigned long long u = draw64(s0, inc, g_D[0] + (unsigned long long)i);
  double dv = (double)(u >> 11) * (1.0 / 9007199254740992.0);
  g_bias[i] = (float)(-1.0 + 2.0 * dv);
}

// ---------------- channel sum ----------------
__global__ void sum_kernel(const float* __restrict__ x) {
  int idx = blockIdx.x * blockDim.x + threadIdx.x;
  if (idx >= 256 * 1024) return;
  int b = idx >> 10, l4 = idx & 1023;
  const float4* xb = (const float4*)(x + (size_t)b * 23 * 4096) + l4;
  float4 a = __ldcs(xb);
#pragma unroll
  for (int c = 1; c < 23; ++c) {
    float4 v = __ldcs(xb + (size_t)c * 1024);
    a.x += v.x; a.y += v.y; a.z += v.z; a.w += v.w;
  }
  ((float4*)g_s)[(size_t)b * 1024 + l4] = a;
}

// ---------------- order-statistic helpers ----------------
DEV unsigned int f2ord(float f) {
  unsigned int b = __float_as_uint(f);
  return (b & 0x80000000u) ? ~b : (b | 0x80000000u);
}

// dual-K conv for one dilation: r7 = 7-tap, r9 = r7 + outer two taps
template <int D>
DEV void conv2K(const float* S, int t, float* r7, float* r9) {
#pragma unroll
  for (int i = 0; i < 16; ++i) {
    int l = t + i * 256 + 128;
    float a = S[l - 3 * D];
    a += S[l - 2 * D]; a += S[l - D]; a += S[l]; a += S[l + D];
    a += S[l + 2 * D]; a += S[l + 3 * D];
    r7[i] = a;
    r9[i] = a + S[l - 4 * D] + S[l + 4 * D];
  }
}

// cold exact path: keys in U; builds pass-0 histogram, radix-selects rank 1351,
// counts(<=key); flag = count < 2704 (i.e. v[1351] < v[2703]).
__device__ __noinline__ void fallback_select(unsigned int* U, unsigned int* hist,
                                             unsigned int* wt, int* sel, int* rci,
                                             int t, int gi) {
  int lane = t & 31, wid = t >> 5;
  hist[t] = 0;
  __syncthreads();
  for (int i = 0; i < 16; ++i)
    atomicAdd(&hist[U[t + i * 256] >> 24], 1u);
  __syncthreads();

#define SCAN_SELECT(rr)                                                        \
  {                                                                            \
    unsigned int oa = hist[t]; unsigned int a = oa;                            \
    for (int o = 1; o < 32; o <<= 1) {                                         \
      unsigned int na = __shfl_up_sync(0xffffffffu, a, o);                     \
      if (lane >= o) a += na;                                                  \
    }                                                                          \
    if (lane == 31) wt[wid] = a;                                               \
    __syncthreads();                                                           \
    if (wid == 0) {                                                            \
      unsigned int va = (lane < 8) ? wt[lane] : 0u;                            \
      for (int o = 1; o < 8; o <<= 1) {                                        \
        unsigned int na = __shfl_up_sync(0xffffffffu, va, o);                  \
        if (lane >= o) va += na;                                               \
      }                                                                        \
      if (lane < 8) wt[lane] = va;                                             \
    }                                                                          \
    __syncthreads();                                                           \
    a += wid ? wt[wid - 1] : 0u;                                               \
    unsigned int lo = a - oa;                                                  \
    if ((unsigned)(rr) >= lo && (unsigned)(rr) < a) { sel[0] = t; sel[1] = (int)lo; } \
    __syncthreads();                                                           \
  }

  int rA = 1351; unsigned int pA = 0;
  SCAN_SELECT(rA);
  pA = ((unsigned int)sel[0]) << 24; rA -= sel[1];

  for (int p = 1; p < 4; ++p) {
    int shift = 24 - 8 * p;
    unsigned int maskHi = 0xFFFFFFFFu << (32 - 8 * p);
    hist[t] = 0;
    __syncthreads();
    for (int i = 0; i < 16; ++i) {
      unsigned int key = U[t + i * 256];
      if (((key ^ pA) & maskHi) == 0)
        atomicAdd(&hist[(key >> shift) & 255u], 1u);
    }
    __syncthreads();
    SCAN_SELECT(rA);
    pA |= ((unsigned int)sel[0]) << shift; rA -= sel[1];
  }

  int cnt = 0;
  for (int i = 0; i < 16; ++i) cnt += (U[t + i * 256] <= pA) ? 1 : 0;
  for (int o = 16; o; o >>= 1) cnt += __shfl_xor_sync(0xffffffffu, cnt, o);
  if (lane == 0) rci[wid] = cnt;
  __syncthreads();
  if (t == 0) {
    int total = 0;
    for (int i = 0; i < 8; ++i) total += rci[i];
    g_t[gi] = (total < 2704) ? 1.0f : 0.0f;
  }
#undef SCAN_SELECT
}

// ---------------- main per-(batch,dilation) kernel: both K=7 and K=9 ----------------
// Hot path (4 barriers): conv -> {max,sum} reduce -> pivot=mean -> count(<=pivot)
// via shared atomic counters; if count in [1352,2703] then v[1351] <= p < v[2703]
// => flag=1 exactly. Cold path: full radix select.
__global__ void __launch_bounds__(256) main_kernel() {
  __shared__ __align__(16) unsigned int buf[4352];  // pad128 | data4096 | pad128
  __shared__ unsigned int hist[256];
  __shared__ unsigned int wt[8];
  __shared__ int sel[2];
  __shared__ float redA[8], redB[8], sumA[8], sumB[8];
  __shared__ float pivots[2];
  __shared__ int cnt2[2];
  __shared__ int rci[8];

  int b = blockIdx.x, dexp = blockIdx.y;
  int t = threadIdx.x, lane = t & 31, wid = t >> 5;

  float* S = (float*)buf;
  unsigned int* U = buf + 128;

  if (t < 128) buf[t] = 0; else buf[4096 + t] = 0;
  if (t < 2) cnt2[t] = 0;
  {
    const float4* src = (const float4*)(g_s + (size_t)b * 4096);
    float4* dstS = (float4*)(S + 128);
#pragma unroll
    for (int i = 0; i < 4; ++i) dstS[t + i * 256] = src[t + i * 256];
  }
  __syncthreads();                                   // (1)

  float r7[16], r9[16];
  switch (dexp) {
    case 0:  conv2K<1>(S, t, r7, r9);  break;
    case 1:  conv2K<2>(S, t, r7, r9);  break;
    case 2:  conv2K<4>(S, t, r7, r9);  break;
    case 3:  conv2K<8>(S, t, r7, r9);  break;
    case 4:  conv2K<16>(S, t, r7, r9); break;
    default: conv2K<32>(S, t, r7, r9); break;
  }

  float mxA = r7[0], mxB = r9[0], smA = r7[0], smB = r9[0];
#pragma unroll
  for (int i = 1; i < 16; ++i) {
    mxA = fmaxf(mxA, r7[i]); smA += r7[i];
    mxB = fmaxf(mxB, r9[i]); smB += r9[i];
  }
  for (int o = 16; o; o >>= 1) {
    mxA = fmaxf(mxA, __shfl_xor_sync(0xffffffffu, mxA, o));
    mxB = fmaxf(mxB, __shfl_xor_sync(0xffffffffu, mxB, o));
    smA += __shfl_xor_sync(0xffffffffu, smA, o);
    smB += __shfl_xor_sync(0xffffffffu, smB, o);
  }
  if (lane == 0) { redA[wid] = mxA; redB[wid] = mxB; sumA[wid] = smA; sumB[wid] = smB; }
  __syncthreads();                                   // (2)

  int giA = b * 12 + dexp, giB = b * 12 + 6 + dexp;
  if (t == 0) {
    float bmA = redA[0], bmB = redB[0], tsA = sumA[0], tsB = sumB[0];
#pragma unroll
    for (int i = 1; i < 8; ++i) {
      bmA = fmaxf(bmA, redA[i]); bmB = fmaxf(bmB, redB[i]);
      tsA += sumA[i]; tsB += sumB[i];
    }
    g_m[giA] = bmA; g_m[giB] = bmB;
    pivots[0] = tsA * (1.0f / 4096.0f);
    pivots[1] = tsB * (1.0f / 4096.0f);
  }
  __syncthreads();                                   // (3)

  float pA = pivots[0], pB = pivots[1];
  int cA = 0, cB = 0;
#pragma unroll
  for (int i = 0; i < 16; ++i) {
    cA += (r7[i] <= pA) ? 1 : 0;
    cB += (r9[i] <= pB) ? 1 : 0;
  }
  for (int o = 16; o; o >>= 1) {
    cA += __shfl_xor_sync(0xffffffffu, cA, o);
    cB += __shfl_xor_sync(0xffffffffu, cB, o);
  }
  if (lane == 0) { atomicAdd(&cnt2[0], cA); atomicAdd(&cnt2[1], cB); }
  __syncthreads();                                   // (4)

  int tA = cnt2[0], tB = cnt2[1];
  bool okA = (tA >= 1352 && tA <= 2703);
  bool okB = (tB >= 1352 && tB <= 2703);
  if (t == 0) {
    if (okA) g_t[giA] = 1.0f;
    if (okB) g_t[giB] = 1.0f;
  }
  if (okA && okB) return;                            // certified hot path

  if (!okA) {
#pragma unroll
    for (int i = 0; i < 16; ++i) U[t + i * 256] = f2ord(r7[i]);
    __syncthreads();
    fallback_select(U, hist, wt, sel, rci, t, giA);
  }
  if (!okB) {
    __syncthreads();
#pragma unroll
    for (int i = 0; i < 16; ++i) U[t + i * 256] = f2ord(r9[i]);
    __syncthreads();
    fallback_select(U, hist, wt, sel, rci, t, giB);
  }
}

// ---------------- output writer (float4 = 2 feature pairs) ----------------
__global__ void out_kernel(float* __restrict__ out) {
  int j = blockIdx.x * blockDim.x + threadIdx.x;   // 0..4999
  int b = blockIdx.y;
  if (j >= 5000) return;
  int i0 = 2 * j, i1 = 2 * j + 1;
  int g0 = g_group[i0], g1 = g_group[i1];
  float4 v;
  v.x = (g_m[b * 12 + g0] > g_bias[i0]) ? 1.0f : 0.0f;
  v.y = g_t[b * 12 + g0];
  v.z = (g_m[b * 12 + g1] > g_bias[i1]) ? 1.0f : 0.0f;
  v.w = g_t[b * 12 + g1];
  ((float4*)out)[(size_t)b * 5000 + j] = v;
}

extern "C" void kernel_launch(void* const* d_in, const int* in_sizes, int n_in,
                              void* d_out, int out_size) {
  const float* x = (const float*)d_in[0];
  float* out = (float*)d_out;
  cfg1_kernel<<<(20048 + 255) / 256, 256>>>();
  cfg2_kernel<<<1, 1024>>>();
  cfg3_kernel<<<(10000 + 255) / 256, 256>>>();
  sum_kernel<<<(256 * 1024 + 255) / 256, 256>>>(x);
  main_kernel<<<dim3(256, 6), 256>>>();
  out_kernel<<<dim3(20, 256), 256>>>(out);
}